// round 1
// baseline (speedup 1.0000x reference)
#include <cuda_runtime.h>
#include <math.h>

// Problem constants
#define NB 16        // B = b*h
#define TLEN 4096    // sequence length
#define NHASH 8
#define NBUCK 64     // local buckets per round
#define NGBUCK 512   // global buckets per B-row
#define CHUNKS 512   // chunks per B-row
#define CS 64        // chunk size
#define E 64         // head dim

// Scratch (device globals — no allocations allowed)
__device__ unsigned char g_buckets[NB * NHASH * TLEN];       // local bucket per (B,nh,t)
__device__ int   g_counts [NB * NGBUCK];
__device__ int   g_offsets[NB * NGBUCK];
__device__ int   g_st     [NB * NHASH * TLEN];               // sorted token ids
__device__ float g_logits [NB * NHASH * TLEN];               // per-round lse at (B,nh,t)
__device__ float g_o      [(size_t)NB * NHASH * TLEN * E];   // per-round outputs (128MB)

__global__ void zero_counts_kernel() {
    int i = blockIdx.x * blockDim.x + threadIdx.x;
    if (i < NB * NGBUCK) g_counts[i] = 0;
}

// One warp per (B, t): 8 rounds x 32 rotation dots over e=64, argmax over [rot, -rot]
__global__ void hash_kernel(const float* __restrict__ qk, const float* __restrict__ rot) {
    int gwarp = blockIdx.x * 8 + (threadIdx.x >> 5);   // 0 .. 65535
    int lane = threadIdx.x & 31;
    int B = gwarp >> 12;
    int t = gwarp & (TLEN - 1);
    int b = B >> 3, hh = B & 7;

    __shared__ float sq[8][64];
    int wl = threadIdx.x >> 5;
    const float* qrow = qk + (((size_t)(b * TLEN + t)) * 8 + hh) * E;
    sq[wl][lane]      = qrow[lane];
    sq[wl][lane + 32] = qrow[lane + 32];
    __syncwarp();

    for (int nh = 0; nh < NHASH; nh++) {
        float acc = 0.f;
        #pragma unroll
        for (int e = 0; e < E; e++)
            acc = fmaf(sq[wl][e], rot[(e * NHASH + nh) * 32 + lane], acc);
        // candidates: (acc, lane) and (-acc, lane+32); jnp.argmax = first max
        float bestv; int besti;
        if (-acc > acc) { bestv = -acc; besti = lane + 32; }
        else            { bestv =  acc; besti = lane; }
        #pragma unroll
        for (int off = 16; off; off >>= 1) {
            float ov = __shfl_down_sync(0xffffffffu, bestv, off);
            int   oi = __shfl_down_sync(0xffffffffu, besti, off);
            if (ov > bestv || (ov == bestv && oi < besti)) { bestv = ov; besti = oi; }
        }
        besti = __shfl_sync(0xffffffffu, besti, 0);
        if (lane == 0) {
            g_buckets[(B * NHASH + nh) * TLEN + t] = (unsigned char)besti;
            atomicAdd(&g_counts[B * NGBUCK + nh * NBUCK + besti], 1);
        }
    }
}

__global__ void scan_kernel() {
    int B = blockIdx.x;
    if (threadIdx.x == 0) {
        int acc = 0;
        for (int g = 0; g < NGBUCK; g++) {
            g_offsets[B * NGBUCK + g] = acc;
            acc += g_counts[B * NGBUCK + g];
        }
    }
}

// Stable counting-sort scatter: block per (B, nh), thread = bucket, scan t ascending
__global__ void scatter_kernel() {
    int B = blockIdx.x >> 3, nh = blockIdx.x & 7;
    __shared__ unsigned char sb[TLEN];
    const unsigned char* src = &g_buckets[(B * NHASH + nh) * TLEN];
    for (int i = threadIdx.x; i < TLEN; i += 64) sb[i] = src[i];
    __syncthreads();

    int bucket = threadIdx.x;  // 0..63
    int pos = g_offsets[B * NGBUCK + nh * NBUCK + bucket];
    for (int t = 0; t < TLEN; t++)
        if (sb[t] == bucket) g_st[B * (NHASH * TLEN) + pos++] = t;
}

// Block per (B, chunk): 64 queries x 128 keys (chunk + look-back chunk).
// Keys = normalized queries; normalization folded into per-row scalar inv-norm.
__global__ void attn_kernel(const float* __restrict__ qk, const float* __restrict__ vv) {
    extern __shared__ float sm[];
    float* sk   = sm;                 // 128 x 65
    float* sv   = sm + 128 * 65;      // 128 x 65
    float* invn = sv + 128 * 65;      // 128
    float* sp   = invn + 128;         // 8 warps x 128
    __shared__ int stk[128];

    int tid = threadIdx.x;
    int Bq = blockIdx.x >> 9;
    int c  = blockIdx.x & (CHUNKS - 1);
    int cp = (c + CHUNKS - 1) & (CHUNKS - 1);
    int b = Bq >> 3, hh = Bq & 7;

    if (tid < 128) {
        int p = (tid < 64) ? (c * CS + tid) : (cp * CS + tid - 64);
        stk[tid] = g_st[Bq * (NHASH * TLEN) + p];
    }
    __syncthreads();

    // Gather 128 rows of qk and v
    int e = tid & 63, rg = tid >> 6;
    for (int j = rg; j < 128; j += 4) {
        int t = stk[j];
        size_t base = ((size_t)((b * TLEN + t) * 8 + hh)) * E;
        sk[j * 65 + e] = qk[base + e];
        sv[j * 65 + e] = vv[base + e];
    }
    __syncthreads();

    if (tid < 128) {
        float ss = 0.f;
        #pragma unroll
        for (int q = 0; q < E; q++) { float x = sk[tid * 65 + q]; ss = fmaf(x, x, ss); }
        invn[tid] = 1.f / fmaxf(sqrtf(ss), 1e-12f);
    }
    __syncthreads();

    int w = tid >> 5, lane = tid & 31;
    int nh = c >> 6;

    for (int rr = 0; rr < 8; rr++) {
        int i = w * 8 + rr;           // query row 0..63
        int ti = stk[i];
        float d0 = 0.f, d1 = 0.f, d2 = 0.f, d3 = 0.f;
        const float* qrow = &sk[i * 65];
        #pragma unroll
        for (int q = 0; q < E; q++) {
            float qv = qrow[q];
            d0 = fmaf(qv, sk[(lane      ) * 65 + q], d0);
            d1 = fmaf(qv, sk[(lane + 32 ) * 65 + q], d1);
            d2 = fmaf(qv, sk[(lane + 64 ) * 65 + q], d2);
            d3 = fmaf(qv, sk[(lane + 96 ) * 65 + q], d3);
        }
        d0 *= invn[lane]; d1 *= invn[lane + 32]; d2 *= invn[lane + 64]; d3 *= invn[lane + 96];
        if (stk[lane]      == ti) d0 = -50000.f;
        if (stk[lane + 32] == ti) d1 = -50000.f;
        if (stk[lane + 64] == ti) d2 = -50000.f;
        if (stk[lane + 96] == ti) d3 = -50000.f;

        float mx = fmaxf(fmaxf(d0, d1), fmaxf(d2, d3));
        #pragma unroll
        for (int off = 16; off; off >>= 1) mx = fmaxf(mx, __shfl_xor_sync(0xffffffffu, mx, off));
        float e0 = expf(d0 - mx), e1 = expf(d1 - mx), e2 = expf(d2 - mx), e3 = expf(d3 - mx);
        float s = e0 + e1 + e2 + e3;
        #pragma unroll
        for (int off = 16; off; off >>= 1) s += __shfl_xor_sync(0xffffffffu, s, off);
        float inv = 1.f / s;

        sp[w * 128 + lane]      = e0 * inv;
        sp[w * 128 + lane + 32] = e1 * inv;
        sp[w * 128 + lane + 64] = e2 * inv;
        sp[w * 128 + lane + 96] = e3 * inv;
        __syncwarp();

        float a0 = 0.f, a1 = 0.f;
        #pragma unroll
        for (int j = 0; j < 128; j++) {
            float pj = sp[w * 128 + j];
            a0 = fmaf(pj, sv[j * 65 + lane],      a0);
            a1 = fmaf(pj, sv[j * 65 + lane + 32], a1);
        }
        size_t orow = ((size_t)((Bq * NHASH + nh) * TLEN + ti)) * E;
        g_o[orow + lane]      = a0;
        g_o[orow + lane + 32] = a1;
        if (lane == 0) g_logits[(Bq * NHASH + nh) * TLEN + ti] = mx + logf(s);
        __syncwarp();
    }
}

// Combine rounds: softmax over 8 per-round lse's, weighted sum of per-round outputs
__global__ void combine_kernel(float* __restrict__ out) {
    int gid = blockIdx.x * blockDim.x + threadIdx.x;   // NB*TLEN*E threads
    int d = gid & 63;
    int token = gid >> 6;                               // 0..65535
    int B = token >> 12, t = token & (TLEN - 1);

    float l[NHASH];
    float mx = -INFINITY;
    #pragma unroll
    for (int nh = 0; nh < NHASH; nh++) {
        l[nh] = g_logits[(B * NHASH + nh) * TLEN + t];
        mx = fmaxf(mx, l[nh]);
    }
    float s = 0.f;
    #pragma unroll
    for (int nh = 0; nh < NHASH; nh++) { l[nh] = expf(l[nh] - mx); s += l[nh]; }
    float inv = 1.f / s;
    float acc = 0.f;
    #pragma unroll
    for (int nh = 0; nh < NHASH; nh++)
        acc = fmaf(l[nh] * inv, g_o[((size_t)((B * NHASH + nh) * TLEN + t)) * E + d], acc);
    out[((size_t)token) * E + d] = acc;
}

extern "C" void kernel_launch(void* const* d_in, const int* in_sizes, int n_in,
                              void* d_out, int out_size) {
    const float* qk  = (const float*)d_in[0];
    // d_in[1] = k is unused by the reference (shared-QK attention)
    const float* v   = (const float*)d_in[2];
    const float* rot = (const float*)d_in[3];
    float* out = (float*)d_out;

    const int attn_smem = (128 * 65 * 2 + 128 + 8 * 128) * (int)sizeof(float); // 71168 B
    cudaFuncSetAttribute(attn_kernel, cudaFuncAttributeMaxDynamicSharedMemorySize, attn_smem);

    zero_counts_kernel<<<32, 256>>>();
    hash_kernel<<<NB * TLEN / 8, 256>>>(qk, rot);
    scan_kernel<<<NB, 32>>>();
    scatter_kernel<<<NB * NHASH, 64>>>();
    attn_kernel<<<NB * CHUNKS, 256, attn_smem>>>(qk, v);
    combine_kernel<<<NB * TLEN * E / 256, 256>>>(out);
}

// round 3
// speedup vs baseline: 2.1013x; 2.1013x over previous
#include <cuda_runtime.h>
#include <math.h>

// Problem constants
#define NB 16        // B = b*h
#define TLEN 4096    // sequence length
#define NHASH 8
#define NBUCK 64     // local buckets per round
#define NGBUCK 512   // global buckets per B-row
#define CHUNKS 512   // chunks per B-row
#define CS 64        // chunk size
#define E 64         // head dim
#define STR 68       // smem row stride for 64-wide rows (float4-aligned, conflict-free)
#define PSTR 132     // smem row stride for 128-wide prob rows (float4-aligned)

// Scratch (device globals — no allocations allowed)
__device__ unsigned char g_buckets[NB * NHASH * TLEN];       // local bucket per (B,nh,t)
__device__ int   g_counts [NB * NGBUCK];
__device__ int   g_offsets[NB * NGBUCK];
__device__ int   g_st     [NB * NHASH * TLEN];               // sorted token ids
__device__ float g_logits [NB * NHASH * TLEN];               // per-round lse at (B,nh,t)
__device__ float g_o      [(size_t)NB * NHASH * TLEN * E];   // per-round outputs (128MB)

__global__ void zero_counts_kernel() {
    int i = blockIdx.x * blockDim.x + threadIdx.x;
    if (i < NB * NGBUCK) g_counts[i] = 0;
}

// Block = (B, 64-token group). Rotations staged in smem (transposed), 8 tokens/warp.
__global__ void __launch_bounds__(256, 2) hash_kernel(const float* __restrict__ qk,
                                                      const float* __restrict__ rot) {
    extern __shared__ float hsm[];
    float* srot = hsm;               // 256 rows (nh*32+i) x STR, cols = e
    float* sq   = srot + 256 * STR;  // 64 tokens x STR

    int tid = threadIdx.x;
    int B  = blockIdx.x >> 6;
    int t0 = (blockIdx.x & 63) << 6;
    int b = B >> 3, hh = B & 7;

    // Stage rotations transposed: srot[(nh*32+i)][e] = rot[e*256 + nh*32+i]
    for (int idx = tid; idx < 64 * NHASH * 32; idx += 256) {
        int e = idx >> 8, r = idx & 255;
        srot[r * STR + e] = rot[idx];
    }
    // Stage 64 query rows (coalesced float4)
    for (int idx = tid; idx < 64 * 16; idx += 256) {
        int tok = idx >> 4, e4 = (idx & 15) << 2;
        const float* q = qk + (((size_t)(b * TLEN + t0 + tok)) * 8 + hh) * E;
        *(float4*)&sq[tok * STR + e4] = *(const float4*)&q[e4];
    }
    __syncthreads();

    int w = tid >> 5, lane = tid & 31;
    int r0 = w * 8;   // this warp's 8 tokens

    for (int nh = 0; nh < NHASH; nh++) {
        float acc[8];
        #pragma unroll
        for (int r = 0; r < 8; r++) acc[r] = 0.f;
        const float* rrow = &srot[(nh * 32 + lane) * STR];
        #pragma unroll 4
        for (int e4 = 0; e4 < 64; e4 += 4) {
            float4 rv = *(const float4*)&rrow[e4];
            #pragma unroll
            for (int r = 0; r < 8; r++) {
                float4 qv = *(const float4*)&sq[(r0 + r) * STR + e4];
                acc[r] = fmaf(qv.x, rv.x, fmaf(qv.y, rv.y, fmaf(qv.z, rv.z, fmaf(qv.w, rv.w, acc[r]))));
            }
        }
        #pragma unroll
        for (int r = 0; r < 8; r++) {
            float a = acc[r];
            float bestv; int besti;
            if (-a > a) { bestv = -a; besti = lane + 32; }
            else        { bestv =  a; besti = lane; }
            #pragma unroll
            for (int off = 16; off; off >>= 1) {
                float ov = __shfl_down_sync(0xffffffffu, bestv, off);
                int   oi = __shfl_down_sync(0xffffffffu, besti, off);
                if (ov > bestv || (ov == bestv && oi < besti)) { bestv = ov; besti = oi; }
            }
            besti = __shfl_sync(0xffffffffu, besti, 0);
            if (lane == 0) {
                int t = t0 + r0 + r;
                g_buckets[(B * NHASH + nh) * TLEN + t] = (unsigned char)besti;
                atomicAdd(&g_counts[B * NGBUCK + nh * NBUCK + besti], 1);
            }
        }
    }
}

// Exclusive scan over 512 buckets per B (Hillis-Steele in shared)
__global__ void scan_kernel() {
    __shared__ int s[NGBUCK];
    int B = blockIdx.x, tid = threadIdx.x;
    s[tid] = g_counts[B * NGBUCK + tid];
    __syncthreads();
    for (int off = 1; off < NGBUCK; off <<= 1) {
        int v = (tid >= off) ? s[tid - off] : 0;
        __syncthreads();
        s[tid] += v;
        __syncthreads();
    }
    g_offsets[B * NGBUCK + tid] = tid ? s[tid - 1] : 0;
}

// Stable counting-sort scatter: block per (B, nh), 256 threads, 16 passes.
// Rank within pass via __match_any ballots + per-warp bucket histograms.
__global__ void scatter_kernel() {
    int B = blockIdx.x >> 3, nh = blockIdx.x & 7;
    __shared__ int cnt[NBUCK];
    __shared__ int wcnt[8][NBUCK];
    int tid = threadIdx.x, w = tid >> 5, lane = tid & 31;

    if (tid < NBUCK) cnt[tid] = g_offsets[B * NGBUCK + nh * NBUCK + tid];
    const unsigned char* src = &g_buckets[(B * NHASH + nh) * TLEN];
    int* dst = &g_st[B * (NHASH * TLEN)];

    for (int pass = 0; pass < 16; pass++) {
        wcnt[w][lane] = 0; wcnt[w][lane + 32] = 0;
        __syncthreads();
        int t = pass * 256 + tid;
        int bk = src[t];
        unsigned mask = __match_any_sync(0xffffffffu, bk);
        int rank = __popc(mask & ((1u << lane) - 1u));
        if (rank == 0) wcnt[w][bk] = __popc(mask);
        __syncthreads();
        int pos = cnt[bk] + rank;
        #pragma unroll
        for (int w2 = 0; w2 < 8; w2++)
            if (w2 < w) pos += wcnt[w2][bk];
        dst[pos] = t;
        __syncthreads();
        if (tid < NBUCK) {
            int s = 0;
            #pragma unroll
            for (int w2 = 0; w2 < 8; w2++) s += wcnt[w2][tid];
            cnt[tid] += s;
        }
        __syncthreads();
    }
}

// Block per (B, chunk): 64 queries x 128 keys. Register-tiled: warp = 8 rows,
// thread = 4 key-cols {l, l+32, l+64, l+96}. float4 smem.
__global__ void __launch_bounds__(256, 2) attn_kernel(const float* __restrict__ qk,
                                                      const float* __restrict__ vv) {
    extern __shared__ float sm[];
    float* sk   = sm;                   // 128 x STR
    float* sv   = sk + 128 * STR;       // 128 x STR
    float* sp   = sv + 128 * STR;       // 64 x PSTR (probs: 128 wide!)
    float* invn = sp + 64 * PSTR;       // 128
    __shared__ int stk[128];

    int tid = threadIdx.x;
    int Bq = blockIdx.x >> 9;
    int c  = blockIdx.x & (CHUNKS - 1);
    int cp = (c + CHUNKS - 1) & (CHUNKS - 1);
    int b = Bq >> 3, hh = Bq & 7;

    if (tid < 128) {
        int p = (tid < 64) ? (c * CS + tid) : (cp * CS + tid - 64);
        stk[tid] = g_st[Bq * (NHASH * TLEN) + p];
    }
    __syncthreads();

    // Gather 128 rows (coalesced float4)
    {
        int e4 = (tid & 15) << 2;
        for (int j = tid >> 4; j < 128; j += 16) {
            size_t base = (((size_t)(b * TLEN + stk[j])) * 8 + hh) * E;
            *(float4*)&sk[j * STR + e4] = *(const float4*)&qk[base + e4];
            *(float4*)&sv[j * STR + e4] = *(const float4*)&vv[base + e4];
        }
    }
    __syncthreads();

    if (tid < 128) {
        float ss = 0.f;
        #pragma unroll
        for (int q = 0; q < E; q += 4) {
            float4 x = *(const float4*)&sk[tid * STR + q];
            ss = fmaf(x.x, x.x, fmaf(x.y, x.y, fmaf(x.z, x.z, fmaf(x.w, x.w, ss))));
        }
        invn[tid] = 1.f / fmaxf(sqrtf(ss), 1e-12f);
    }
    __syncthreads();

    int w = tid >> 5, lane = tid & 31;
    int i0 = w * 8;
    int nh = c >> 6;

    // ---- QK: 8 rows x 4 cols register tile ----
    float acc[8][4];
    #pragma unroll
    for (int r = 0; r < 8; r++) { acc[r][0]=0.f; acc[r][1]=0.f; acc[r][2]=0.f; acc[r][3]=0.f; }

    #pragma unroll 4
    for (int q = 0; q < E; q += 4) {
        float4 k0 = *(const float4*)&sk[(lane      ) * STR + q];
        float4 k1 = *(const float4*)&sk[(lane + 32 ) * STR + q];
        float4 k2 = *(const float4*)&sk[(lane + 64 ) * STR + q];
        float4 k3 = *(const float4*)&sk[(lane + 96 ) * STR + q];
        #pragma unroll
        for (int r = 0; r < 8; r++) {
            float4 qv = *(const float4*)&sk[(i0 + r) * STR + q];
            acc[r][0] = fmaf(qv.x,k0.x, fmaf(qv.y,k0.y, fmaf(qv.z,k0.z, fmaf(qv.w,k0.w, acc[r][0]))));
            acc[r][1] = fmaf(qv.x,k1.x, fmaf(qv.y,k1.y, fmaf(qv.z,k1.z, fmaf(qv.w,k1.w, acc[r][1]))));
            acc[r][2] = fmaf(qv.x,k2.x, fmaf(qv.y,k2.y, fmaf(qv.z,k2.z, fmaf(qv.w,k2.w, acc[r][2]))));
            acc[r][3] = fmaf(qv.x,k3.x, fmaf(qv.y,k3.y, fmaf(qv.z,k3.z, fmaf(qv.w,k3.w, acc[r][3]))));
        }
    }

    float in0 = invn[lane], in1 = invn[lane+32], in2 = invn[lane+64], in3 = invn[lane+96];
    int   tj0 = stk[lane],  tj1 = stk[lane+32],  tj2 = stk[lane+64],  tj3 = stk[lane+96];

    float lse[8]; int tirow[8];
    #pragma unroll
    for (int r = 0; r < 8; r++) {
        int ti = stk[i0 + r]; tirow[r] = ti;
        float d0 = acc[r][0]*in0, d1 = acc[r][1]*in1, d2 = acc[r][2]*in2, d3 = acc[r][3]*in3;
        if (tj0 == ti) d0 = -50000.f;
        if (tj1 == ti) d1 = -50000.f;
        if (tj2 == ti) d2 = -50000.f;
        if (tj3 == ti) d3 = -50000.f;

        float mx = fmaxf(fmaxf(d0, d1), fmaxf(d2, d3));
        #pragma unroll
        for (int off = 16; off; off >>= 1) mx = fmaxf(mx, __shfl_xor_sync(0xffffffffu, mx, off));
        float e0 = expf(d0 - mx), e1 = expf(d1 - mx), e2 = expf(d2 - mx), e3 = expf(d3 - mx);
        float s = e0 + e1 + e2 + e3;
        #pragma unroll
        for (int off = 16; off; off >>= 1) s += __shfl_xor_sync(0xffffffffu, s, off);
        float inv = 1.f / s;
        sp[(i0 + r) * PSTR + lane     ] = e0 * inv;
        sp[(i0 + r) * PSTR + lane + 32] = e1 * inv;
        sp[(i0 + r) * PSTR + lane + 64] = e2 * inv;
        sp[(i0 + r) * PSTR + lane + 96] = e3 * inv;
        lse[r] = mx + logf(s);
    }
    __syncwarp();

    // ---- PV: 8 rows x 2 dims per thread ----
    float a0[8], a1[8];
    #pragma unroll
    for (int r = 0; r < 8; r++) { a0[r] = 0.f; a1[r] = 0.f; }

    #pragma unroll 2
    for (int j4 = 0; j4 < 128; j4 += 4) {
        float4 p4[8];
        #pragma unroll
        for (int r = 0; r < 8; r++) p4[r] = *(const float4*)&sp[(i0 + r) * PSTR + j4];

        float v0, v1;
        v0 = sv[(j4+0)*STR + lane]; v1 = sv[(j4+0)*STR + lane + 32];
        #pragma unroll
        for (int r = 0; r < 8; r++) { a0[r] = fmaf(p4[r].x, v0, a0[r]); a1[r] = fmaf(p4[r].x, v1, a1[r]); }
        v0 = sv[(j4+1)*STR + lane]; v1 = sv[(j4+1)*STR + lane + 32];
        #pragma unroll
        for (int r = 0; r < 8; r++) { a0[r] = fmaf(p4[r].y, v0, a0[r]); a1[r] = fmaf(p4[r].y, v1, a1[r]); }
        v0 = sv[(j4+2)*STR + lane]; v1 = sv[(j4+2)*STR + lane + 32];
        #pragma unroll
        for (int r = 0; r < 8; r++) { a0[r] = fmaf(p4[r].z, v0, a0[r]); a1[r] = fmaf(p4[r].z, v1, a1[r]); }
        v0 = sv[(j4+3)*STR + lane]; v1 = sv[(j4+3)*STR + lane + 32];
        #pragma unroll
        for (int r = 0; r < 8; r++) { a0[r] = fmaf(p4[r].w, v0, a0[r]); a1[r] = fmaf(p4[r].w, v1, a1[r]); }
    }

    #pragma unroll
    for (int r = 0; r < 8; r++) {
        size_t orow = ((size_t)((Bq * NHASH + nh) * TLEN + tirow[r])) * E;
        g_o[orow + lane]      = a0[r];
        g_o[orow + lane + 32] = a1[r];
        if (lane == 0) g_logits[(Bq * NHASH + nh) * TLEN + tirow[r]] = lse[r];
    }
}

// Combine rounds: softmax over 8 per-round lse's, weighted sum of per-round outputs
__global__ void combine_kernel(float* __restrict__ out) {
    int gid = blockIdx.x * blockDim.x + threadIdx.x;   // NB*TLEN*E threads
    int d = gid & 63;
    int token = gid >> 6;                               // 0..65535
    int B = token >> 12, t = token & (TLEN - 1);

    float l[NHASH];
    float mx = -INFINITY;
    #pragma unroll
    for (int nh = 0; nh < NHASH; nh++) {
        l[nh] = g_logits[(B * NHASH + nh) * TLEN + t];
        mx = fmaxf(mx, l[nh]);
    }
    float s = 0.f;
    #pragma unroll
    for (int nh = 0; nh < NHASH; nh++) { l[nh] = expf(l[nh] - mx); s += l[nh]; }
    float inv = 1.f / s;
    float acc = 0.f;
    #pragma unroll
    for (int nh = 0; nh < NHASH; nh++)
        acc = fmaf(l[nh] * inv, g_o[((size_t)((B * NHASH + nh) * TLEN + t)) * E + d], acc);
    out[((size_t)token) * E + d] = acc;
}

extern "C" void kernel_launch(void* const* d_in, const int* in_sizes, int n_in,
                              void* d_out, int out_size) {
    const float* qk  = (const float*)d_in[0];
    // d_in[1] = k is unused by the reference (shared-QK attention)
    const float* v   = (const float*)d_in[2];
    const float* rot = (const float*)d_in[3];
    float* out = (float*)d_out;

    const int attn_smem = (128 * STR * 2 + 64 * PSTR + 128) * (int)sizeof(float); // 103936
    const int hash_smem = (256 * STR + 64 * STR) * (int)sizeof(float);            // 87040
    cudaFuncSetAttribute(attn_kernel, cudaFuncAttributeMaxDynamicSharedMemorySize, attn_smem);
    cudaFuncSetAttribute(hash_kernel, cudaFuncAttributeMaxDynamicSharedMemorySize, hash_smem);

    zero_counts_kernel<<<32, 256>>>();
    hash_kernel<<<NB * 64, 256, hash_smem>>>(qk, rot);
    scan_kernel<<<NB, NGBUCK>>>();
    scatter_kernel<<<NB * NHASH, 256>>>();
    attn_kernel<<<NB * CHUNKS, 256, attn_smem>>>(qk, v);
    combine_kernel<<<NB * TLEN * E / 256, 256>>>(out);
}